// round 1
// baseline (speedup 1.0000x reference)
#include <cuda_runtime.h>
#include <math.h>

#define Nn 32
#define Cc 256
#define ICc 128
#define Hh 32
#define Ww 32
#define Ll 1024
#define DA 9216
#define DOUT 131072
#define EPSf 1e-5f

// ---------------- scratch (device globals; no allocation allowed) ----------
__device__ float g_qt[Nn * Ll * ICc];     // [n][l][o]  (transposed q)  16 MB
__device__ float g_kt[Nn * Ll * ICc];     // [n][l][o]  (transposed k)  16 MB
__device__ float g_f[Nn * DA];            // [n][r*L + l]
__device__ float g_h1[Nn * Cc];           // FFN1 pre-relu accumulator (init to b1)
__device__ float g_h2[Nn * DOUT];         // FFN2 out, LN2'd in place   16 MB
__device__ float g_stats[Nn * 2];         // LN2 partial sums

// ---------------- init: h1 = b1, stats = 0 ---------------------------------
__global__ void k_init(const float* __restrict__ b1) {
    int t = blockIdx.x * blockDim.x + threadIdx.x;  // 8192 threads
    if (t < Nn * Cc) g_h1[t] = b1[t & 255];
    if (t < Nn * 2)  g_stats[t] = 0.f;
}

// ---------------- K1: q/k 1x1 conv GEMM  out[l][o] = sum_c w[o][c] x[c][l] --
// grid (ltile=8, qk=2, n=32), 256 thr, tile 128l x 128o, 8x8 per thread
__global__ void __launch_bounds__(256) k_qk(const float* __restrict__ x,
                                            const float* __restrict__ wq,
                                            const float* __restrict__ wk) {
    int lt = blockIdx.x, qk = blockIdx.y, n = blockIdx.z;
    const float* w = qk ? wk : wq;
    float* out = qk ? g_kt : g_qt;
    int l0 = lt * 128;
    __shared__ float xs[8][128];   // [cc][l]
    __shared__ float ws[8][132];   // [cc][o]
    int t = threadIdx.x;
    int tx = t & 15;               // o-group
    int ty = t >> 4;               // l-group
    float acc[8][8];               // [l][o]
#pragma unroll
    for (int i = 0; i < 8; i++)
#pragma unroll
        for (int j = 0; j < 8; j++) acc[i][j] = 0.f;

    const float* xn = x + (size_t)n * Cc * Ll;
    for (int c0 = 0; c0 < Cc; c0 += 8) {
        for (int idx = t; idx < 8 * 128; idx += 256) {
            int cc = idx >> 7, l = idx & 127;
            xs[cc][l] = xn[(c0 + cc) * Ll + l0 + l];
        }
        for (int idx = t; idx < 8 * 128; idx += 256) {
            int o = idx >> 3, cc = idx & 7;
            ws[cc][o] = w[o * Cc + c0 + cc];
        }
        __syncthreads();
#pragma unroll
        for (int cc = 0; cc < 8; cc++) {
            float4 a0 = *(const float4*)&xs[cc][ty * 4];
            float4 a1 = *(const float4*)&xs[cc][64 + ty * 4];
            float4 b0 = *(const float4*)&ws[cc][tx * 4];
            float4 b1 = *(const float4*)&ws[cc][64 + tx * 4];
            float a[8] = {a0.x, a0.y, a0.z, a0.w, a1.x, a1.y, a1.z, a1.w};
            float b[8] = {b0.x, b0.y, b0.z, b0.w, b1.x, b1.y, b1.z, b1.w};
#pragma unroll
            for (int i = 0; i < 8; i++)
#pragma unroll
                for (int j = 0; j < 8; j++) acc[i][j] += a[i] * b[j];
        }
        __syncthreads();
    }
#pragma unroll
    for (int li = 0; li < 8; li++) {
        int l = l0 + (li < 4 ? ty * 4 + li : 64 + ty * 4 + li - 4);
        float* op = out + ((size_t)n * Ll + l) * ICc;
        *(float4*)&op[tx * 4]      = make_float4(acc[li][0], acc[li][1], acc[li][2], acc[li][3]);
        *(float4*)&op[64 + tx * 4] = make_float4(acc[li][4], acc[li][5], acc[li][6], acc[li][7]);
    }
}

// ---------------- K2: local attention scores, warp per (n,l) ---------------
__global__ void __launch_bounds__(256) k_attn() {
    int gw   = blockIdx.x * 8 + (threadIdx.x >> 5);   // 32768 warps
    int lane = threadIdx.x & 31;
    int n = gw >> 10;
    int l = gw & 1023;
    int h = l >> 5, w = l & 31;
    const float* qp = g_qt + ((size_t)(n << 10) + l) * ICc;
    float4 qv = *(const float4*)&qp[lane * 4];
    float acc[9];
#pragma unroll
    for (int r = 0; r < 9; r++) {
        int hh = h + r / 3 - 1;
        int ww = w + r % 3 - 1;
        float s = 0.f;
        if (hh >= 0 && hh < Hh && ww >= 0 && ww < Ww) {
            const float* kp = g_kt + ((size_t)(n << 10) + (hh << 5) + ww) * ICc;
            float4 kv = *(const float4*)&kp[lane * 4];
            s = qv.x * kv.x + qv.y * kv.y + qv.z * kv.z + qv.w * kv.w;
        }
#pragma unroll
        for (int off = 16; off; off >>= 1) s += __shfl_xor_sync(0xffffffffu, s, off);
        acc[r] = s;
    }
    float val = 0.f;
#pragma unroll
    for (int r = 0; r < 9; r++)
        if (lane == r) val = acc[r];
    if (lane < 9) g_f[(size_t)n * DA + lane * Ll + l] = 2.f * val;   // f + dropout(f) == 2f
}

// ---------------- K3: LayerNorm over d_attn, block per n --------------------
__global__ void __launch_bounds__(256) k_ln1(const float* __restrict__ g1,
                                             const float* __restrict__ be1) {
    int n = blockIdx.x, t = threadIdx.x;
    float* fp = g_f + (size_t)n * DA;
    float s = 0.f, s2 = 0.f;
    for (int j = t; j < DA; j += 256) {
        float v = fp[j];
        s += v; s2 += v * v;
    }
#pragma unroll
    for (int off = 16; off; off >>= 1) {
        s  += __shfl_xor_sync(0xffffffffu, s, off);
        s2 += __shfl_xor_sync(0xffffffffu, s2, off);
    }
    __shared__ float sh[16];
    __shared__ float smu, srs;
    int wid = t >> 5;
    if ((t & 31) == 0) { sh[wid] = s; sh[8 + wid] = s2; }
    __syncthreads();
    if (t == 0) {
        float S = 0.f, S2 = 0.f;
        for (int i = 0; i < 8; i++) { S += sh[i]; S2 += sh[8 + i]; }
        float mu = S / DA;
        float var = S2 / DA - mu * mu;
        smu = mu;
        srs = rsqrtf(var + EPSf);
    }
    __syncthreads();
    float mu = smu, rs = srs;
    for (int j = t; j < DA; j += 256) {
        float v = fp[j];
        fp[j] = (v - mu) * rs * g1[j] + be1[j];
    }
}

// ---------------- K4: FFN1 split-K:  h1 += f @ w1.T ------------------------
// grid (16 c-tiles x 24 k-splits), 256 thr, tile [32n x 16c], k-slice 384
__global__ void __launch_bounds__(256) k_ffn1(const float* __restrict__ w1) {
    int c0 = blockIdx.x * 16;
    int jbase = blockIdx.y * 384;
    __shared__ float fs[32][33];
    __shared__ float ws[16][33];
    int t = threadIdx.x;
    int n = t & 31, cg = t >> 5;      // cg 0..7 -> c pair
    int c = c0 + cg * 2;
    float acc0 = 0.f, acc1 = 0.f;
    for (int jc = 0; jc < 12; jc++) {
        int j0 = jbase + jc * 32;
        {
            int nn = t >> 3, jj = (t & 7) * 4;
            float4 v = *(const float4*)&g_f[(size_t)nn * DA + j0 + jj];
            fs[nn][jj] = v.x; fs[nn][jj + 1] = v.y; fs[nn][jj + 2] = v.z; fs[nn][jj + 3] = v.w;
        }
        for (int idx = t; idx < 512; idx += 256) {
            int cl = idx >> 5, jj = idx & 31;
            ws[cl][jj] = w1[(size_t)(c0 + cl) * DA + j0 + jj];
        }
        __syncthreads();
#pragma unroll
        for (int jj = 0; jj < 32; jj++) {
            float fv = fs[n][jj];
            acc0 += fv * ws[cg * 2][jj];
            acc1 += fv * ws[cg * 2 + 1][jj];
        }
        __syncthreads();
    }
    atomicAdd(&g_h1[n * Cc + c],     acc0);
    atomicAdd(&g_h1[n * Cc + c + 1], acc1);
}

// ---------------- K5: FFN2  h2[n][m] = sum_c relu(h1[n][c]) w2[m][c] + b2 --
// grid 256 blocks (512 m each), 256 thr, tile [32n x 512m], 8x8 per thread
__global__ void __launch_bounds__(256) k_ffn2(const float* __restrict__ w2,
                                              const float* __restrict__ b2) {
    int m0 = blockIdx.x * 512;
    __shared__ float hs[256][33];   // [c][n], relu applied
    __shared__ float ws[8][516];    // [cc][m]
    int t = threadIdx.x;
    for (int idx = t; idx < Nn * Cc; idx += 256) {
        int cl = idx & 255, nl = idx >> 8;
        hs[cl][nl] = fmaxf(g_h1[nl * Cc + cl], 0.f);
    }
    __syncthreads();
    int tm = t & 63, tn = t >> 6;
    float acc[8][8];                // [n][m]
#pragma unroll
    for (int i = 0; i < 8; i++)
#pragma unroll
        for (int j = 0; j < 8; j++) acc[i][j] = 0.f;

    for (int c0 = 0; c0 < Cc; c0 += 8) {
        for (int idx = t; idx < 4096; idx += 256) {
            int m = idx >> 3, cc = idx & 7;
            ws[cc][m] = w2[(size_t)(m0 + m) * Cc + c0 + cc];
        }
        __syncthreads();
#pragma unroll
        for (int cc = 0; cc < 8; cc++) {
            const float* hrow = &hs[c0 + cc][0];
            float a[8];
#pragma unroll
            for (int i = 0; i < 4; i++) {
                a[i]     = hrow[tn * 4 + i];
                a[4 + i] = hrow[16 + tn * 4 + i];
            }
            float4 b0 = *(const float4*)&ws[cc][tm * 4];
            float4 b1 = *(const float4*)&ws[cc][256 + tm * 4];
            float b[8] = {b0.x, b0.y, b0.z, b0.w, b1.x, b1.y, b1.z, b1.w};
#pragma unroll
            for (int i = 0; i < 8; i++)
#pragma unroll
                for (int j = 0; j < 8; j++) acc[i][j] += a[i] * b[j];
        }
        __syncthreads();
    }
    float4 bv0 = *(const float4*)&b2[m0 + tm * 4];
    float4 bv1 = *(const float4*)&b2[m0 + 256 + tm * 4];
#pragma unroll
    for (int ni = 0; ni < 8; ni++) {
        int nl = (ni < 4) ? tn * 4 + ni : 16 + tn * 4 + ni - 4;
        float* hp = g_h2 + (size_t)nl * DOUT + m0;
        *(float4*)&hp[tm * 4] = make_float4(acc[ni][0] + bv0.x, acc[ni][1] + bv0.y,
                                            acc[ni][2] + bv0.z, acc[ni][3] + bv0.w);
        *(float4*)&hp[256 + tm * 4] = make_float4(acc[ni][4] + bv1.x, acc[ni][5] + bv1.y,
                                                  acc[ni][6] + bv1.z, acc[ni][7] + bv1.w);
    }
}

// ---------------- K6a: LN2 partial stats ------------------------------------
__global__ void __launch_bounds__(256) k_ln2a() {
    int sl = blockIdx.x, n = blockIdx.y, t = threadIdx.x;
    const float* hp = g_h2 + (size_t)n * DOUT + sl * 8192;
    float s = 0.f, s2 = 0.f;
    for (int j = t * 4; j < 8192; j += 1024) {
        float4 v = *(const float4*)&hp[j];
        s  += v.x + v.y + v.z + v.w;
        s2 += v.x * v.x + v.y * v.y + v.z * v.z + v.w * v.w;
    }
#pragma unroll
    for (int off = 16; off; off >>= 1) {
        s  += __shfl_xor_sync(0xffffffffu, s, off);
        s2 += __shfl_xor_sync(0xffffffffu, s2, off);
    }
    __shared__ float sh[16];
    int wid = t >> 5;
    if ((t & 31) == 0) { sh[wid] = s; sh[8 + wid] = s2; }
    __syncthreads();
    if (t == 0) {
        float S = 0.f, S2 = 0.f;
        for (int i = 0; i < 8; i++) { S += sh[i]; S2 += sh[8 + i]; }
        atomicAdd(&g_stats[n * 2],     S);
        atomicAdd(&g_stats[n * 2 + 1], S2);
    }
}

// ---------------- K6b: LN2 normalize (in place) -----------------------------
__global__ void __launch_bounds__(256) k_ln2b(const float* __restrict__ g2,
                                              const float* __restrict__ be2) {
    int sl = blockIdx.x, n = blockIdx.y, t = threadIdx.x;
    float mu  = g_stats[n * 2] * (1.f / DOUT);
    float var = g_stats[n * 2 + 1] * (1.f / DOUT) - mu * mu;
    float rs  = rsqrtf(var + EPSf);
    float* hp = g_h2 + (size_t)n * DOUT + sl * 8192;
    const float* gp = g2 + sl * 8192;
    const float* bp = be2 + sl * 8192;
    for (int j = t * 4; j < 8192; j += 1024) {
        float4 v = *(const float4*)&hp[j];
        float4 gg = *(const float4*)&gp[j];
        float4 bb = *(const float4*)&bp[j];
        v.x = (v.x - mu) * rs * gg.x + bb.x;
        v.y = (v.y - mu) * rs * gg.y + bb.y;
        v.z = (v.z - mu) * rs * gg.z + bb.z;
        v.w = (v.w - mu) * rs * gg.w + bb.w;
        *(float4*)&hp[j] = v;
    }
}

// ---------------- K7: out conv + BN + residual ------------------------------
// out[c][l] = sum_o wout[c][o] * y[o][l]; grid (ltile=8, ctile=2, n=32)
__global__ void __launch_bounds__(256) k_out(const float* __restrict__ x,
                                             const float* __restrict__ wout,
                                             const float* __restrict__ bng,
                                             const float* __restrict__ bnb,
                                             const float* __restrict__ bnm,
                                             const float* __restrict__ bnv,
                                             float* __restrict__ out) {
    int lt = blockIdx.x, ct = blockIdx.y, n = blockIdx.z;
    int l0 = lt * 128, c0 = ct * 128;
    __shared__ float as[8][128];   // [oo][l]
    __shared__ float ws[8][132];   // [oo][c]
    int t = threadIdx.x;
    int tx = t & 15;               // l-group
    int ty = t >> 4;               // c-group
    float acc[8][8];               // [c][l]
#pragma unroll
    for (int i = 0; i < 8; i++)
#pragma unroll
        for (int j = 0; j < 8; j++) acc[i][j] = 0.f;

    const float* yn = g_h2 + (size_t)n * DOUT;   // [o][l] layout
    for (int o0 = 0; o0 < ICc; o0 += 8) {
        for (int idx = t; idx < 8 * 128; idx += 256) {
            int oo = idx >> 7, l = idx & 127;
            as[oo][l] = yn[(o0 + oo) * Ll + l0 + l];
        }
        for (int idx = t; idx < 8 * 128; idx += 256) {
            int cl = idx >> 3, oo = idx & 7;
            ws[oo][cl] = wout[(size_t)(c0 + cl) * ICc + o0 + oo];
        }
        __syncthreads();
#pragma unroll
        for (int oo = 0; oo < 8; oo++) {
            float4 a0 = *(const float4*)&as[oo][tx * 4];
            float4 a1 = *(const float4*)&as[oo][64 + tx * 4];
            float4 b0 = *(const float4*)&ws[oo][ty * 4];
            float4 b1 = *(const float4*)&ws[oo][64 + ty * 4];
            float a[8] = {a0.x, a0.y, a0.z, a0.w, a1.x, a1.y, a1.z, a1.w};
            float b[8] = {b0.x, b0.y, b0.z, b0.w, b1.x, b1.y, b1.z, b1.w};
#pragma unroll
            for (int ci = 0; ci < 8; ci++)
#pragma unroll
                for (int li = 0; li < 8; li++) acc[ci][li] += b[ci] * a[li];
        }
        __syncthreads();
    }
#pragma unroll
    for (int ci = 0; ci < 8; ci++) {
        int c = c0 + (ci < 4 ? ty * 4 + ci : 64 + ty * 4 + ci - 4);
        float sc = bng[c] * rsqrtf(bnv[c] + EPSf);
        float mb = bnm[c], bb = bnb[c];
        size_t base = ((size_t)n * Cc + c) * Ll + l0;
        {
            float4 xv = *(const float4*)&x[base + tx * 4];
            float4 r;
            r.x = (acc[ci][0] - mb) * sc + bb + xv.x;
            r.y = (acc[ci][1] - mb) * sc + bb + xv.y;
            r.z = (acc[ci][2] - mb) * sc + bb + xv.z;
            r.w = (acc[ci][3] - mb) * sc + bb + xv.w;
            *(float4*)&out[base + tx * 4] = r;
        }
        {
            float4 xv = *(const float4*)&x[base + 64 + tx * 4];
            float4 r;
            r.x = (acc[ci][4] - mb) * sc + bb + xv.x;
            r.y = (acc[ci][5] - mb) * sc + bb + xv.y;
            r.z = (acc[ci][6] - mb) * sc + bb + xv.z;
            r.w = (acc[ci][7] - mb) * sc + bb + xv.w;
            *(float4*)&out[base + 64 + tx * 4] = r;
        }
    }
}

// ---------------- launch -----------------------------------------------------
extern "C" void kernel_launch(void* const* d_in, const int* in_sizes, int n_in,
                              void* d_out, int out_size) {
    const float* x      = (const float*)d_in[0];
    const float* wq     = (const float*)d_in[1];
    const float* wk     = (const float*)d_in[2];
    const float* gamma1 = (const float*)d_in[3];
    const float* beta1  = (const float*)d_in[4];
    const float* w1     = (const float*)d_in[5];
    const float* b1     = (const float*)d_in[6];
    const float* w2     = (const float*)d_in[7];
    const float* b2     = (const float*)d_in[8];
    const float* gamma2 = (const float*)d_in[9];
    const float* beta2  = (const float*)d_in[10];
    const float* w_out  = (const float*)d_in[11];
    const float* bn_g   = (const float*)d_in[12];
    const float* bn_b   = (const float*)d_in[13];
    const float* bn_m   = (const float*)d_in[14];
    const float* bn_v   = (const float*)d_in[15];
    float* out = (float*)d_out;

    k_init<<<32, 256>>>(b1);
    k_qk<<<dim3(8, 2, 32), 256>>>(x, wq, wk);
    k_attn<<<4096, 256>>>();
    k_ln1<<<32, 256>>>(gamma1, beta1);
    k_ffn1<<<dim3(16, 24), 256>>>(w1);
    k_ffn2<<<256, 256>>>(w2, b2);
    k_ln2a<<<dim3(16, 32), 256>>>();
    k_ln2b<<<dim3(16, 32), 256>>>(gamma2, beta2);
    k_out<<<dim3(8, 2, 32), 256>>>(x, w_out, bn_g, bn_b, bn_m, bn_v, out);
}

// round 3
// speedup vs baseline: 2.2697x; 2.2697x over previous
#include <cuda_runtime.h>
#include <cuda_bf16.h>
#include <cstdint>
#include <math.h>

#define Nn 32
#define Cc 256
#define ICc 128
#define Hh 32
#define Ww 32
#define Ll 1024
#define DA 9216
#define DOUT 131072
#define EPSf 1e-5f

// ---------------- scratch ----------------------------------------------------
__device__ float g_qt[Nn * Ll * ICc];     // [n][l][o]
__device__ float g_kt[Nn * Ll * ICc];     // [n][l][o]
__device__ float g_f[Nn * DA];
__device__ float g_h1[Nn * Cc];
__device__ float g_h2[Nn * DOUT];         // [n][m]
__device__ float g_stats[Nn * 2];

// ---------------- mma.sync helpers (compute_103-safe) ------------------------
__device__ __forceinline__ uint32_t s2u(const void* p) {
    uint32_t a;
    asm("{ .reg .u64 t; cvta.to.shared.u64 t, %1; cvt.u32.u64 %0, t; }" : "=r"(a) : "l"(p));
    return a;
}
// SW64 swizzle: rows of 64B, XOR bits[4:5] with bits[7:8]
#define SZ(o) ((uint32_t)(o) ^ ((((uint32_t)(o)) >> 3) & 0x30))

__device__ __forceinline__ void ldsm4(uint32_t* r, uint32_t a) {
    asm volatile("ldmatrix.sync.aligned.m8n8.x4.shared.b16 {%0,%1,%2,%3}, [%4];"
                 : "=r"(r[0]), "=r"(r[1]), "=r"(r[2]), "=r"(r[3]) : "r"(a));
}
__device__ __forceinline__ void mma16816(float* d, const uint32_t* a, uint32_t b0, uint32_t b1) {
    asm volatile(
        "mma.sync.aligned.m16n8k16.row.col.f32.bf16.bf16.f32 "
        "{%0,%1,%2,%3}, {%4,%5,%6,%7}, {%8,%9}, {%0,%1,%2,%3};"
        : "+f"(d[0]), "+f"(d[1]), "+f"(d[2]), "+f"(d[3])
        : "r"(a[0]), "r"(a[1]), "r"(a[2]), "r"(a[3]), "r"(b0), "r"(b1));
}

__device__ __forceinline__ uint32_t bf2u(__nv_bfloat16 a, __nv_bfloat16 b) {
    return (uint32_t)__bfloat16_as_ushort(a) | ((uint32_t)__bfloat16_as_ushort(b) << 16);
}
__device__ __forceinline__ void split2(float a, float b, uint32_t& hi, uint32_t& lo) {
    __nv_bfloat16 ha = __float2bfloat16(a), hb = __float2bfloat16(b);
    __nv_bfloat16 la = __float2bfloat16(a - __bfloat162float(ha));
    __nv_bfloat16 lb = __float2bfloat16(b - __bfloat162float(hb));
    hi = bf2u(ha, hb);
    lo = bf2u(la, lb);
}

// 3-pass hi/lo MMA over one K=32 chunk; block tile 128x128, warp tile 32x64.
// acc[2][8][4]; aoff[mi][ks], boff[p][ks] are SZ'd smem offsets (hi planes).
__device__ __forceinline__ void chunk_128x128(float (&acc)[2][8][4], uint32_t base,
                                              const uint32_t (&aoff)[2][2],
                                              const uint32_t (&boff)[4][2],
                                              uint32_t aLo, uint32_t bLo) {
#pragma unroll
    for (int ks = 0; ks < 2; ks++) {
        uint32_t ah0[4], ah1[4], al0[4], al1[4];
        ldsm4(ah0, base + aoff[0][ks]);
        ldsm4(ah1, base + aoff[1][ks]);
        ldsm4(al0, base + aoff[0][ks] + aLo);
        ldsm4(al1, base + aoff[1][ks] + aLo);
#pragma unroll
        for (int p = 0; p < 4; p++) {
            uint32_t bh[4], bl[4];
            ldsm4(bh, base + boff[p][ks]);
            ldsm4(bl, base + boff[p][ks] + bLo);
            mma16816(acc[0][2 * p],     ah0, bh[0], bh[1]);
            mma16816(acc[0][2 * p + 1], ah0, bh[2], bh[3]);
            mma16816(acc[1][2 * p],     ah1, bh[0], bh[1]);
            mma16816(acc[1][2 * p + 1], ah1, bh[2], bh[3]);
            mma16816(acc[0][2 * p],     ah0, bl[0], bl[1]);
            mma16816(acc[0][2 * p + 1], ah0, bl[2], bl[3]);
            mma16816(acc[1][2 * p],     ah1, bl[0], bl[1]);
            mma16816(acc[1][2 * p + 1], ah1, bl[2], bl[3]);
            mma16816(acc[0][2 * p],     al0, bh[0], bh[1]);
            mma16816(acc[0][2 * p + 1], al0, bh[2], bh[3]);
            mma16816(acc[1][2 * p],     al1, bh[0], bh[1]);
            mma16816(acc[1][2 * p + 1], al1, bh[2], bh[3]);
        }
    }
}
// block tile 256x32, warp tile 32x32
__device__ __forceinline__ void chunk_256x32(float (&acc)[2][4][4], uint32_t base,
                                             const uint32_t (&aoff)[2][2],
                                             const uint32_t (&boff)[2][2],
                                             uint32_t aLo, uint32_t bLo) {
#pragma unroll
    for (int ks = 0; ks < 2; ks++) {
        uint32_t ah0[4], ah1[4], al0[4], al1[4];
        ldsm4(ah0, base + aoff[0][ks]);
        ldsm4(ah1, base + aoff[1][ks]);
        ldsm4(al0, base + aoff[0][ks] + aLo);
        ldsm4(al1, base + aoff[1][ks] + aLo);
#pragma unroll
        for (int p = 0; p < 2; p++) {
            uint32_t bh[4], bl[4];
            ldsm4(bh, base + boff[p][ks]);
            ldsm4(bl, base + boff[p][ks] + bLo);
            mma16816(acc[0][2 * p],     ah0, bh[0], bh[1]);
            mma16816(acc[0][2 * p + 1], ah0, bh[2], bh[3]);
            mma16816(acc[1][2 * p],     ah1, bh[0], bh[1]);
            mma16816(acc[1][2 * p + 1], ah1, bh[2], bh[3]);
            mma16816(acc[0][2 * p],     ah0, bl[0], bl[1]);
            mma16816(acc[0][2 * p + 1], ah0, bl[2], bl[3]);
            mma16816(acc[1][2 * p],     ah1, bl[0], bl[1]);
            mma16816(acc[1][2 * p + 1], ah1, bl[2], bl[3]);
            mma16816(acc[0][2 * p],     al0, bh[0], bh[1]);
            mma16816(acc[0][2 * p + 1], al0, bh[2], bh[3]);
            mma16816(acc[1][2 * p],     al1, bh[0], bh[1]);
            mma16816(acc[1][2 * p + 1], al1, bh[2], bh[3]);
        }
    }
}

// precompute SZ'd ldmatrix offsets for a 128x128 (or 256x32) tile
__device__ __forceinline__ void mk_aoff(uint32_t (&aoff)[2][2], int m_off, int lane,
                                        uint32_t planeA) {
    int sub = lane >> 3, rr = lane & 7;
#pragma unroll
    for (int mi = 0; mi < 2; mi++)
#pragma unroll
        for (int ks = 0; ks < 2; ks++) {
            int row = m_off + mi * 16 + (sub & 1) * 8 + rr;
            int byte = ks * 32 + (sub >> 1) * 16;
            aoff[mi][ks] = planeA + SZ(row * 64 + byte);
        }
}
template <int NP>
__device__ __forceinline__ void mk_boff(uint32_t (&boff)[NP][2], int n_off, int lane,
                                        uint32_t planeB) {
    int sub = lane >> 3, rr = lane & 7;
#pragma unroll
    for (int p = 0; p < NP; p++)
#pragma unroll
        for (int ks = 0; ks < 2; ks++) {
            int row = n_off + p * 16 + (sub >> 1) * 8 + rr;
            int byte = ks * 32 + (sub & 1) * 16;
            boff[p][ks] = planeB + SZ(row * 64 + byte);
        }
}

// ====================== K1: q/k conv  D[l][o] = sum_c x[c][l] w[o][c] ========
// planes: AH 0 | AL 8192 | BH 16384 | BL 24576 ; buf 32768 x2
#define GK_BUF 32768
#define GK_SMEM (2 * GK_BUF)
__global__ void __launch_bounds__(256) k_qk_mma(const float* __restrict__ x,
                                                const float* __restrict__ wq,
                                                const float* __restrict__ wk) {
    extern __shared__ char sm[];
    const int lt = blockIdx.x, qk = blockIdx.y, n = blockIdx.z;
    const float* w = qk ? wk : wq;
    float* outp = qk ? g_kt : g_qt;
    const int l0 = lt * 128;
    uint32_t sb = s2u(sm);
    int t = threadIdx.x, wid = t >> 5, lane = t & 31;
    int wm = wid >> 1, wn = wid & 1;
    int gid = lane >> 2, tig = lane & 3;

    uint32_t aoff[2][2], boff[4][2];
    mk_aoff(aoff, wm * 32, lane, 0u);
    mk_boff<4>(boff, wn * 64, lane, 16384u);

    float acc[2][8][4];
#pragma unroll
    for (int i = 0; i < 2; i++)
#pragma unroll
        for (int j = 0; j < 8; j++)
#pragma unroll
            for (int q = 0; q < 4; q++) acc[i][j][q] = 0.f;

    const int la = t & 127, cg = t >> 7;
    const float* xc = x + (size_t)n * Cc * Ll + l0 + la;

    float sa[4][4];   // A stage (transpose of x)
    float4 sbv[4];    // B stage (w rows)

#define K1_LOAD(c0) {                                                          \
    _Pragma("unroll")                                                          \
    for (int it = 0; it < 4; it++) {                                           \
        int ck = (it * 2 + cg) * 4;                                            \
        sa[it][0] = xc[(size_t)((c0) + ck + 0) * Ll];                          \
        sa[it][1] = xc[(size_t)((c0) + ck + 1) * Ll];                          \
        sa[it][2] = xc[(size_t)((c0) + ck + 2) * Ll];                          \
        sa[it][3] = xc[(size_t)((c0) + ck + 3) * Ll];                          \
    }                                                                          \
    _Pragma("unroll")                                                          \
    for (int it = 0; it < 4; it++) {                                           \
        int idx = it * 256 + t;                                                \
        int row = idx >> 3, c4 = (idx & 7) * 4;                                \
        sbv[it] = *(const float4*)&w[(size_t)row * Cc + (c0) + c4];            \
    } }
#define K1_STORE(bsel) {                                                       \
    uint32_t bo = (bsel) * GK_BUF;                                             \
    _Pragma("unroll")                                                          \
    for (int it = 0; it < 4; it++) {                                           \
        int ck = (it * 2 + cg) * 4;                                            \
        uint32_t h0, lo0, h1, lo1;                                             \
        split2(sa[it][0], sa[it][1], h0, lo0);                                 \
        split2(sa[it][2], sa[it][3], h1, lo1);                                 \
        uint32_t off = SZ(la * 64 + ck * 2);                                   \
        *(uint2*)(sm + bo + off)        = make_uint2(h0, h1);                  \
        *(uint2*)(sm + bo + 8192 + off) = make_uint2(lo0, lo1);                \
    }                                                                          \
    _Pragma("unroll")                                                          \
    for (int it = 0; it < 4; it++) {                                           \
        int idx = it * 256 + t;                                                \
        int row = idx >> 3, c4 = (idx & 7) * 4;                                \
        uint32_t h0, lo0, h1, lo1;                                             \
        split2(sbv[it].x, sbv[it].y, h0, lo0);                                 \
        split2(sbv[it].z, sbv[it].w, h1, lo1);                                 \
        uint32_t off = SZ(row * 64 + c4 * 2);                                  \
        *(uint2*)(sm + bo + 16384 + off) = make_uint2(h0, h1);                 \
        *(uint2*)(sm + bo + 24576 + off) = make_uint2(lo0, lo1);               \
    } }

    K1_LOAD(0);
    K1_STORE(0);
    __syncthreads();
#pragma unroll 1
    for (int c = 0; c < 8; c++) {
        if (c + 1 < 8) K1_LOAD((c + 1) * 32);
        chunk_128x128(acc, sb + (c & 1) * GK_BUF, aoff, boff, 8192u, 8192u);
        if (c + 1 < 8) K1_STORE((c + 1) & 1);
        __syncthreads();
    }
    // epilogue: direct writes, D rows = l, cols = o
#pragma unroll
    for (int mi = 0; mi < 2; mi++)
#pragma unroll
        for (int r2 = 0; r2 < 2; r2++) {
            int l = l0 + wm * 32 + mi * 16 + gid + r2 * 8;
            float* op = outp + ((size_t)(n << 10) + l) * ICc + wn * 64;
#pragma unroll
            for (int nj = 0; nj < 8; nj++)
                *(float2*)&op[nj * 8 + tig * 2] =
                    make_float2(acc[mi][nj][r2 * 2], acc[mi][nj][r2 * 2 + 1]);
        }
}

// ====================== K2: local attention =================================
__global__ void __launch_bounds__(256) k_attn() {
    int gw = blockIdx.x * 8 + (threadIdx.x >> 5);
    int lane = threadIdx.x & 31;
    int n = gw >> 10;
    int l = gw & 1023;
    int h = l >> 5, w = l & 31;
    const float* qp = g_qt + ((size_t)(n << 10) + l) * ICc;
    float4 qv = *(const float4*)&qp[lane * 4];
    float acc[9];
#pragma unroll
    for (int r = 0; r < 9; r++) {
        int hh = h + r / 3 - 1;
        int ww = w + r % 3 - 1;
        float s = 0.f;
        if (hh >= 0 && hh < Hh && ww >= 0 && ww < Ww) {
            const float* kp = g_kt + ((size_t)(n << 10) + (hh << 5) + ww) * ICc;
            float4 kv = *(const float4*)&kp[lane * 4];
            s = qv.x * kv.x + qv.y * kv.y + qv.z * kv.z + qv.w * kv.w;
        }
#pragma unroll
        for (int off = 16; off; off >>= 1) s += __shfl_xor_sync(0xffffffffu, s, off);
        acc[r] = s;
    }
    float val = 0.f;
#pragma unroll
    for (int r = 0; r < 9; r++)
        if (lane == r) val = acc[r];
    if (lane < 9) g_f[(size_t)n * DA + lane * Ll + l] = 2.f * val;
}

// ---------------- init --------------------------------------------------------
__global__ void k_init(const float* __restrict__ b1) {
    int t = blockIdx.x * blockDim.x + threadIdx.x;
    if (t < Nn * Cc) g_h1[t] = b1[t & 255];
    if (t < Nn * 2)  g_stats[t] = 0.f;
}

// ---------------- LN1: 1024 threads, float4 -----------------------------------
__global__ void __launch_bounds__(1024) k_ln1(const float* __restrict__ g1,
                                              const float* __restrict__ be1) {
    int n = blockIdx.x, t = threadIdx.x;
    float4* fp4 = (float4*)(g_f + (size_t)n * DA);
    const float4* g4 = (const float4*)g1;
    const float4* b4 = (const float4*)be1;
    float s = 0.f, s2 = 0.f;
    for (int j = t; j < DA / 4; j += 1024) {
        float4 v = fp4[j];
        s  += v.x + v.y + v.z + v.w;
        s2 += v.x * v.x + v.y * v.y + v.z * v.z + v.w * v.w;
    }
#pragma unroll
    for (int off = 16; off; off >>= 1) {
        s  += __shfl_xor_sync(0xffffffffu, s, off);
        s2 += __shfl_xor_sync(0xffffffffu, s2, off);
    }
    __shared__ float sh[64];
    __shared__ float smu, srs;
    int wid = t >> 5;
    if ((t & 31) == 0) { sh[wid] = s; sh[32 + wid] = s2; }
    __syncthreads();
    if (t == 0) {
        float S = 0.f, S2 = 0.f;
        for (int i = 0; i < 32; i++) { S += sh[i]; S2 += sh[32 + i]; }
        float mu = S / DA;
        smu = mu;
        srs = rsqrtf(S2 / DA - mu * mu + EPSf);
    }
    __syncthreads();
    float mu = smu, rs = srs;
    for (int j = t; j < DA / 4; j += 1024) {
        float4 v = fp4[j];
        float4 gg = g4[j], bb = b4[j];
        v.x = (v.x - mu) * rs * gg.x + bb.x;
        v.y = (v.y - mu) * rs * gg.y + bb.y;
        v.z = (v.z - mu) * rs * gg.z + bb.z;
        v.w = (v.w - mu) * rs * gg.w + bb.w;
        fp4[j] = v;
    }
}

// ---------------- FFN1 split-K (unchanged) ------------------------------------
__global__ void __launch_bounds__(256) k_ffn1(const float* __restrict__ w1) {
    int c0 = blockIdx.x * 16;
    int jbase = blockIdx.y * 384;
    __shared__ float fs[32][33];
    __shared__ float ws[16][33];
    int t = threadIdx.x;
    int n = t & 31, cg = t >> 5;
    int c = c0 + cg * 2;
    float acc0 = 0.f, acc1 = 0.f;
    for (int jc = 0; jc < 12; jc++) {
        int j0 = jbase + jc * 32;
        {
            int nn = t >> 3, jj = (t & 7) * 4;
            float4 v = *(const float4*)&g_f[(size_t)nn * DA + j0 + jj];
            fs[nn][jj] = v.x; fs[nn][jj + 1] = v.y; fs[nn][jj + 2] = v.z; fs[nn][jj + 3] = v.w;
        }
        for (int idx = t; idx < 512; idx += 256) {
            int cl = idx >> 5, jj = idx & 31;
            ws[cl][jj] = w1[(size_t)(c0 + cl) * DA + j0 + jj];
        }
        __syncthreads();
#pragma unroll
        for (int jj = 0; jj < 32; jj++) {
            float fv = fs[n][jj];
            acc0 += fv * ws[cg * 2][jj];
            acc1 += fv * ws[cg * 2 + 1][jj];
        }
        __syncthreads();
    }
    atomicAdd(&g_h1[n * Cc + c],     acc0);
    atomicAdd(&g_h1[n * Cc + c + 1], acc1);
}

// ====================== K5: FFN2  D[m][nb] = w2[m][:]·relu(h1[nb][:]) ========
// planes: AH 0 (16K) | AL 16384 | BH 32768 (2K) | BL 34816 ; buf 36864 x2
#define F2_BUF 36864
#define F2_SMEM (2 * F2_BUF)
__global__ void __launch_bounds__(256) k_ffn2_mma(const float* __restrict__ w2,
                                                  const float* __restrict__ b2) {
    extern __shared__ char sm[];
    const int m0 = blockIdx.x * 256;
    uint32_t sb = s2u(sm);
    int t = threadIdx.x, wid = t >> 5, lane = t & 31;
    int gid = lane >> 2, tig = lane & 3;

    uint32_t aoff[2][2], boff[2][2];
    mk_aoff(aoff, wid * 32, lane, 0u);
    mk_boff<2>(boff, 0, lane, 32768u);

    float acc[2][4][4];
#pragma unroll
    for (int i = 0; i < 2; i++)
#pragma unroll
        for (int j = 0; j < 4; j++)
#pragma unroll
            for (int q = 0; q < 4; q++) acc[i][j][q] = 0.f;

    float4 sav[8];
    float4 sbv;

#define F2_LOAD(c0) {                                                          \
    _Pragma("unroll")                                                          \
    for (int it = 0; it < 8; it++) {                                           \
        int idx = it * 256 + t;                                                \
        int row = idx >> 3, c4 = (idx & 7) * 4;                                \
        sav[it] = *(const float4*)&w2[(size_t)(m0 + row) * Cc + (c0) + c4];    \
    }                                                                          \
    {                                                                          \
        int row = t >> 3, c4 = (t & 7) * 4;                                    \
        float4 v = *(const float4*)&g_h1[(size_t)row * Cc + (c0) + c4];        \
        v.x = fmaxf(v.x, 0.f); v.y = fmaxf(v.y, 0.f);                          \
        v.z = fmaxf(v.z, 0.f); v.w = fmaxf(v.w, 0.f);                          \
        sbv = v;                                                               \
    } }
#define F2_STORE(bsel) {                                                       \
    uint32_t bo = (bsel) * F2_BUF;                                             \
    _Pragma("unroll")                                                          \
    for (int it = 0; it < 8; it++) {                                           \
        int idx = it * 256 + t;                                                \
        int row = idx >> 3, c4 = (idx & 7) * 4;                                \
        uint32_t h0, lo0, h1, lo1;                                             \
        split2(sav[it].x, sav[it].y, h0, lo0);                                 \
        split2(sav[it].z, sav[it].w, h1, lo1);                                 \
        uint32_t off = SZ(row * 64 + c4 * 2);                                  \
        *(uint2*)(sm + bo + off)         = make_uint2(h0, h1);                 \
        *(uint2*)(sm + bo + 16384 + off) = make_uint2(lo0, lo1);               \
    }                                                                          \
    {                                                                          \
        int row = t >> 3, c4 = (t & 7) * 4;                                    \
        uint32_t h0, lo0, h1, lo1;                                             \
        split2(sbv.x, sbv.y, h0, lo0);                                         \
        split2(sbv.z, sbv.w, h1, lo1);                                         \
        uint32_t off = SZ(row * 64 + c4 * 2);                                  \
        *(uint2*)(sm + bo + 32768 + off) = make_uint2(h0, h1);                 \
        *(uint2*)(sm + bo + 34816 + off) = make_uint2(lo0, lo1);               \
    } }

    F2_LOAD(0);
    F2_STORE(0);
    __syncthreads();
#pragma unroll 1
    for (int c = 0; c < 8; c++) {
        if (c + 1 < 8) F2_LOAD((c + 1) * 32);
        chunk_256x32(acc, sb + (c & 1) * F2_BUF, aoff, boff, 16384u, 2048u);
        if (c + 1 < 8) F2_STORE((c + 1) & 1);
        __syncthreads();
    }
    // epilogue: stage [32n][260] fp32 in smem, then coalesced writes + bias
    __syncthreads();
    float* ep = (float*)sm;
#pragma unroll
    for (int mi = 0; mi < 2; mi++)
#pragma unroll
        for (int nj = 0; nj < 4; nj++) {
            int m = wid * 32 + mi * 16 + gid;
            int cN = nj * 8 + tig * 2;
            ep[cN * 260 + m]           = acc[mi][nj][0];
            ep[(cN + 1) * 260 + m]     = acc[mi][nj][1];
            ep[cN * 260 + m + 8]       = acc[mi][nj][2];
            ep[(cN + 1) * 260 + m + 8] = acc[mi][nj][3];
        }
    __syncthreads();
#pragma unroll
    for (int it = 0; it < 8; it++) {
        int idx = it * 256 + t;
        int nn = idx >> 6, c4 = (idx & 63) * 4;
        float4 v = *(float4*)&ep[nn * 260 + c4];
        float4 bv = *(const float4*)&b2[m0 + c4];
        v.x += bv.x; v.y += bv.y; v.z += bv.z; v.w += bv.w;
        *(float4*)&g_h2[(size_t)nn * DOUT + m0 + c4] = v;
    }
}

// ---------------- LN2 ---------------------------------------------------------
__global__ void __launch_bounds__(256) k_ln2a() {
    int sl = blockIdx.x, n = blockIdx.y, t = threadIdx.x;
    const float* hp = g_h2 + (size_t)n * DOUT + sl * 8192;
    float s = 0.f, s2 = 0.f;
    for (int j = t * 4; j < 8192; j += 1024) {
        float4 v = *(const float4*)&hp[j];
        s  += v.x + v.y + v.z + v.w;
        s2 += v.x * v.x + v.y * v.y + v.z * v.z + v.w * v.w;
    }
#pragma unroll
    for (int off = 16; off; off >>= 1) {
        s  += __shfl_xor_sync(0xffffffffu, s, off);
        s2 += __shfl_xor_sync(0xffffffffu, s2, off);
    }
    __shared__ float sh[16];
    int wid = t >> 5;
    if ((t & 31) == 0) { sh[wid] = s; sh[8 + wid] = s2; }
    __syncthreads();
    if (t == 0) {
        float S = 0.f, S2 = 0.f;
        for (int i = 0; i < 8; i++) { S += sh[i]; S2 += sh[8 + i]; }
        atomicAdd(&g_stats[n * 2],     S);
        atomicAdd(&g_stats[n * 2 + 1], S2);
    }
}

__global__ void __launch_bounds__(256) k_ln2b(const float* __restrict__ g2,
                                              const float* __restrict__ be2) {
    int sl = blockIdx.x, n = blockIdx.y, t = threadIdx.x;
    float mu  = g_stats[n * 2] * (1.f / DOUT);
    float var = g_stats[n * 2 + 1] * (1.f / DOUT) - mu * mu;
    float rs  = rsqrtf(var + EPSf);
    float* hp = g_h2 + (size_t)n * DOUT + sl * 8192;
    const float* gp = g2 + sl * 8192;
    const float* bp = be2 + sl * 8192;
    for (int j = t * 4; j < 8192; j += 1024) {
        float4 v = *(const float4*)&hp[j];
        float4 gg = *(const float4*)&gp[j];
        float4 bb = *(const float4*)&bp[j];
        v.x = (v.x - mu) * rs * gg.x + bb.x;
        v.y = (v.y - mu) * rs * gg.y + bb.y;
        v.z = (v.z - mu) * rs * gg.z + bb.z;
        v.w = (v.w - mu) * rs * gg.w + bb.w;
        *(float4*)&hp[j] = v;
    }
}

// ====================== K7: out conv + BN + residual =========================
// D[c][l] = sum_o wout[c][o] y[o][l]; K=128, 4 chunks
__global__ void __launch_bounds__(256) k_out_mma(const float* __restrict__ x,
                                                 const float* __restrict__ wout,
                                                 const float* __restrict__ bng,
                                                 const float* __restrict__ bnb,
                                                 const float* __restrict__ bnm,
                                                 const float* __restrict__ bnv,
                                                 float* __restrict__ out) {
    extern __shared__ char sm[];
    const int lt = blockIdx.x, ct = blockIdx.y, n = blockIdx.z;
    const int l0 = lt * 128, c0b = ct * 128;
    uint32_t sb = s2u(sm);
    int t = threadIdx.x, wid = t >> 5, lane = t & 31;
    int wm = wid >> 1, wn = wid & 1;
    int gid = lane >> 2, tig = lane & 3;

    uint32_t aoff[2][2], boff[4][2];
    mk_aoff(aoff, wm * 32, lane, 0u);
    mk_boff<4>(boff, wn * 64, lane, 16384u);

    float acc[2][8][4];
#pragma unroll
    for (int i = 0; i < 2; i++)
#pragma unroll
        for (int j = 0; j < 8; j++)
#pragma unroll
            for (int q = 0; q < 4; q++) acc[i][j][q] = 0.f;

    const int la = t & 127, cg = t >> 7;
    const float* yc = g_h2 + (size_t)n * DOUT + l0 + la;

    float4 sav[4];
    float sbr[4][4];

#define K7_LOAD(o0) {                                                          \
    _Pragma("unroll")                                                          \
    for (int it = 0; it < 4; it++) {                                           \
        int idx = it * 256 + t;                                                \
        int row = idx >> 3, c4 = (idx & 7) * 4;                                \
        sav[it] = *(const float4*)&wout[(size_t)(c0b + row) * ICc + (o0) + c4];\
    }                                                                          \
    _Pragma("unroll")                                                          \
    for (int it = 0; it < 4; it++) {                                           \
        int ck = (it * 2 + cg) * 4;                                            \
        sbr[it][0] = yc[(size_t)((o0) + ck + 0) * Ll];                         \
        sbr[it][1] = yc[(size_t)((o0) + ck + 1) * Ll];                         \
        sbr[it][2] = yc[(size_t)((o0) + ck + 2) * Ll];                         \
        sbr[it][3] = yc[(size_t)((o0) + ck + 3) * Ll];                         \
    } }
#define K7_STORE(bsel) {                                                       \
    uint32_t bo = (bsel) * GK_BUF;                                             \
    _Pragma("unroll")                                                          \
    for (int it = 0; it < 4; it++) {                                           \
        int idx = it * 256 + t;                                                \
        int row = idx >> 3, c4 = (idx & 7) * 4;                                \
        uint32_t h0, lo0, h1, lo1;                                             \
        split2(sav[it].x, sav[it].y, h0, lo0);                                 \
        split2(sav[it].z, sav[it].w, h1, lo1);                                 \
        uint32_t off = SZ(row * 64 + c4 * 2);                                  \
        *(uint2*)(sm + bo + off)        = make_uint2(h0, h1);                  \
        *(uint2*)(sm + bo + 8192 + off) = make_uint2(lo0, lo1);                \
    }                                                                          \
    _Pragma("unroll")                                                          \
    for (int it = 0; it < 4; it++) {                                           \
        int ck = (it * 2 + cg) * 4;                                            \
        uint32_t h0, lo0, h1, lo1;                                             \
        split2(sbr[it][0], sbr[it][1], h0, lo0);                               \
        split2(sbr[it][2], sbr[it][3], h1, lo1);                               \
        uint32_t off = SZ(la * 64 + ck * 2);                                   \
        *(uint2*)(sm + bo + 16384 + off) = make_uint2(h0, h1);                 \
        *(uint2*)(sm + bo + 24576 + off) = make_uint2(lo0, lo1);               \
    } }

    K7_LOAD(0);
    K7_STORE(0);
    __syncthreads();
#pragma unroll 1
    for (int c = 0; c < 4; c++) {
        if (c + 1 < 4) K7_LOAD((c + 1) * 32);
        chunk_128x128(acc, sb + (c & 1) * GK_BUF, aoff, boff, 8192u, 8192u);
        if (c + 1 < 4) K7_STORE((c + 1) & 1);
        __syncthreads();
    }
    // epilogue: BN + residual, rows = c, cols = l
#pragma unroll
    for (int mi = 0; mi < 2; mi++)
#pragma unroll
        for (int r2 = 0; r2 < 2; r2++) {
            int c = c0b + wm * 32 + mi * 16 + gid + r2 * 8;
            float sc = bng[c] * rsqrtf(bnv[c] + EPSf);
            float mb = bnm[c], bb = bnb[c];
            size_t base = ((size_t)n * Cc + c) * Ll + l0 + wn * 64;
#pragma unroll
            for (int nj = 0; nj < 8; nj++) {
                int lo = nj * 8 + tig * 2;
                float2 xv = *(const float2*)&x[base + lo];
                float2 o;
                o.x = (acc[mi][nj][r2 * 2]     - mb) * sc + bb + xv.x;
                o.y = (acc[mi][nj][r2 * 2 + 1] - mb) * sc + bb + xv.y;
                *(float2*)&out[base + lo] = o;
            }
        }
}

// ---------------- launch -------------------------------------------------------
extern "C" void kernel_launch(void* const* d_in, const int* in_sizes, int n_in,
                              void* d_out, int out_size) {
    const float* x      = (const float*)d_in[0];
    const float* wq     = (const float*)d_in[1];
    const float* wk     = (const float*)d_in[2];
    const float* gamma1 = (const float*)d_in[3];
    const float* beta1  = (const float*)d_in[4];
    const float* w1     = (const float*)d_in[5];
    const float* b1     = (const float*)d_in[6];
    const float* w2     = (const float*)d_in[7];
    const float* b2     = (const float*)d_in[8];
    const float* gamma2 = (const float*)d_in[9];
    const float* beta2  = (const float*)d_in[10];
    const float* w_out  = (const float*)d_in[11];
    const float* bn_g   = (const float*)d_in[12];
    const float* bn_b   = (const float*)d_in[13];
    const float* bn_m   = (const float*)d_in[14];
    const float* bn_v   = (const float*)d_in[15];
    float* out = (float*)d_out;

    cudaFuncSetAttribute(k_qk_mma,   cudaFuncAttributeMaxDynamicSharedMemorySize, GK_SMEM);
    cudaFuncSetAttribute(k_ffn2_mma, cudaFuncAttributeMaxDynamicSharedMemorySize, F2_SMEM);
    cudaFuncSetAttribute(k_out_mma,  cudaFuncAttributeMaxDynamicSharedMemorySize, GK_SMEM);

    k_init<<<32, 256>>>(b1);
    k_qk_mma<<<dim3(8, 2, 32), 256, GK_SMEM>>>(x, wq, wk);
    k_attn<<<4096, 256>>>();
    k_ln1<<<32, 1024>>>(gamma1, beta1);
    k_ffn1<<<dim3(16, 24), 256>>>(w1);
    k_ffn2_mma<<<512, 256, F2_SMEM>>>(w2, b2);
    k_ln2a<<<dim3(16, 32), 256>>>();
    k_ln2b<<<dim3(16, 32), 256>>>(gamma2, beta2);
    k_out_mma<<<dim3(8, 2, 32), 256, GK_SMEM>>>(x, w_out, bn_g, bn_b, bn_m, bn_v, out);
}